// round 1
// baseline (speedup 1.0000x reference)
#include <cuda_runtime.h>
#include <cstdint>

#define NT   340704          // 32*3*(13*13+26*26+52*52)
#define CAP  4096
#define NK   512

// ---------------- scratch (static device globals: no allocation) ------------
__device__ unsigned long long g_keys[NT];
__device__ float              g_boxes[NT * 6];
__device__ unsigned           g_hist1[2048];
__device__ unsigned           g_hist2[2048];
__device__ unsigned           g_cnt;
__device__ int                g_b1;
__device__ int                g_b2;
__device__ unsigned           g_cA1;
__device__ unsigned long long g_gbuf[CAP];
__device__ float              g_cand[NK * 6];
__device__ unsigned char      g_alive[NK];
__device__ float              g_maxp;
__device__ unsigned           g_sup[NK * 16];

// order-preserving float <-> uint mapping
__device__ __forceinline__ unsigned fordf(float f) {
    unsigned u = __float_as_uint(f);
    return (u & 0x80000000u) ? ~u : (u | 0x80000000u);
}
__device__ __forceinline__ float ifordf(unsigned e) {
    return __uint_as_float((e & 0x80000000u) ? (e & 0x7FFFFFFFu) : ~e);
}

// ---------------- init (graph replays must re-zero) -------------------------
__global__ void k_init() {
    int t = blockIdx.x * blockDim.x + threadIdx.x;
    if (t < 2048) { g_hist1[t] = 0; g_hist2[t] = 0; }
    if (t < CAP)  g_gbuf[t] = 0ull;
    if (t == 0)   g_cnt = 0;
}

// ---------------- decode one scale ------------------------------------------
template <int S>
__global__ void k_decode(const float* __restrict__ out,
                         const float* __restrict__ anchors,
                         const float* __restrict__ c1p,
                         const float* __restrict__ c2p,
                         int goff) {
    __shared__ unsigned shist[2048];
    for (int i = threadIdx.x; i < 2048; i += blockDim.x) shist[i] = 0;
    __syncthreads();

    const int SS = S * S;
    const int total = 32 * 3 * SS;
    int t = blockIdx.x * blockDim.x + threadIdx.x;
    if (t < total) {
        int plane = t / SS;
        int cell  = t - plane * SS;
        int y = cell / S;
        int x = cell - y * S;
        int b = plane / 3;
        int a = plane - 3 * b;
        const float* pc = out + ((size_t)b * 255 + (size_t)a * 85) * SS + cell;
        int g = goff + (b * SS + cell) * 3 + a;      // reference flatten order

        float o0  = pc[0];
        float obj = 1.f / (1.f + expf(-o0));
        float score;
        if (obj > 0.5f) {
            float o1 = pc[1 * SS], o2 = pc[2 * SS], o3 = pc[3 * SS], o4 = pc[4 * SS];
            float m = -1e30f; int am = 0; float sum = 0.f;
#pragma unroll 4
            for (int c = 0; c < 80; ++c) {
                float l = pc[(size_t)(5 + c) * SS];
                sum += expf(l);
                if (l > m) { m = l; am = c; }        // first max wins (argmax)
            }
            float p  = obj * (expf(m) / sum);
            float c1 = *c1p, c2 = *c2p;
            const float s1 = 416.f / (float)S;
            float cx = ((float)x + o1) * s1 / c1;
            float cy = ((float)y + o2) * s1 / c2;
            float w  = expf(o3) * anchors[a * 2 + 0] / c1;
            float h  = expf(o4) * anchors[a * 2 + 1] / c2;
            float* bx = g_boxes + (size_t)g * 6;
            bx[0] = p; bx[1] = cx; bx[2] = cy; bx[3] = w; bx[4] = h; bx[5] = (float)am;
            score = p;
        } else {
            score = -1.0f;   // invalid: never selected-alive -> box values unused
        }
        unsigned fs = fordf(score);
        g_keys[goff + t] = ((unsigned long long)fs << 32) | (unsigned)(~(unsigned)g);
        atomicAdd(&shist[fs >> 21], 1u);
    }
    __syncthreads();
    for (int i = threadIdx.x; i < 2048; i += blockDim.x) {
        unsigned v = shist[i];
        if (v) atomicAdd(&g_hist1[i], v);
    }
}

// ---------------- radix-select level 1 --------------------------------------
__global__ void k_select1() {
    __shared__ unsigned sa[2048], sb[2048];
    int tid = threadIdx.x;                      // 1024 threads
    for (int i = tid; i < 2048; i += 1024) sa[i] = g_hist1[i];
    __syncthreads();
    unsigned* src = sa; unsigned* dst = sb;
    for (int off = 1; off < 2048; off <<= 1) {
        for (int i = tid; i < 2048; i += 1024) {
            unsigned v = src[i];
            if (i + off < 2048) v += src[i + off];
            dst[i] = v;
        }
        __syncthreads();
        unsigned* tmp = src; src = dst; dst = tmp;
    }
    for (int i = tid; i < 2048; i += 1024) {
        bool cross = (src[i] >= (unsigned)NK) && (i == 2047 || src[i + 1] < (unsigned)NK);
        if (cross) { g_b1 = i; g_cA1 = (i == 2047) ? 0u : src[i + 1]; }
    }
}

__global__ void k_hist2() {
    int t = blockIdx.x * blockDim.x + threadIdx.x;
    if (t >= NT) return;
    unsigned long long k = g_keys[t];
    if ((int)(unsigned)(k >> 53) == g_b1)
        atomicAdd(&g_hist2[(unsigned)(k >> 42) & 2047u], 1u);
}

__global__ void k_select2() {
    __shared__ unsigned sa[2048], sb[2048];
    int tid = threadIdx.x;
    unsigned target = (unsigned)NK - g_cA1;     // >= 1
    for (int i = tid; i < 2048; i += 1024) sa[i] = g_hist2[i];
    __syncthreads();
    unsigned* src = sa; unsigned* dst = sb;
    for (int off = 1; off < 2048; off <<= 1) {
        for (int i = tid; i < 2048; i += 1024) {
            unsigned v = src[i];
            if (i + off < 2048) v += src[i + off];
            dst[i] = v;
        }
        __syncthreads();
        unsigned* tmp = src; src = dst; dst = tmp;
    }
    for (int i = tid; i < 2048; i += 1024) {
        bool cross = (src[i] >= target) && (i == 2047 || src[i + 1] < target);
        if (cross) g_b2 = i;
    }
}

__global__ void k_gather() {
    int t = blockIdx.x * blockDim.x + threadIdx.x;
    if (t >= NT) return;
    unsigned long long k = g_keys[t];
    int b1 = (int)(unsigned)(k >> 53);
    int b2 = (int)((unsigned)(k >> 42) & 2047u);
    int B1 = g_b1, B2 = g_b2;
    if (b1 > B1 || (b1 == B1 && b2 >= B2)) {
        unsigned pos = atomicAdd(&g_cnt, 1u);
        if (pos < (unsigned)CAP) g_gbuf[pos] = k;
    }
}

// ---------------- single-block bitonic sort + gather top-512 ----------------
__global__ void k_sort() {
    __shared__ unsigned long long s[CAP];       // 32 KB
    __shared__ float red[1024];
    int tid = threadIdx.x;                      // 1024
    for (int i = tid; i < CAP; i += 1024) s[i] = g_gbuf[i];
    __syncthreads();
    for (int k = 2; k <= CAP; k <<= 1) {
        for (int j = k >> 1; j > 0; j >>= 1) {
            for (int i = tid; i < CAP; i += 1024) {
                int ixj = i ^ j;
                if (ixj > i) {
                    bool up = ((i & k) == 0);
                    unsigned long long a = s[i], b = s[ixj];
                    if ((a > b) == up) { s[i] = b; s[ixj] = a; }
                }
            }
            __syncthreads();
        }
    }
    float p = 0.f;
    if (tid < NK) {
        unsigned long long k = s[CAP - 1 - tid];        // descending
        unsigned fs = (unsigned)(k >> 32);
        float score = ifordf(fs);
        unsigned g = ~(unsigned)k;
        bool alive = score > 0.0f;
        float c0 = 0, c1 = 0, c2 = 0, c3 = 0, c4 = 0, c5 = 0;
        if (alive) {
            const float* bx = g_boxes + (size_t)g * 6;
            c0 = bx[0]; c1 = bx[1]; c2 = bx[2]; c3 = bx[3]; c4 = bx[4]; c5 = bx[5];
            p = c0;
        }
        g_alive[tid] = alive ? 1 : 0;
        float* cd = g_cand + tid * 6;
        cd[0] = c0; cd[1] = c1; cd[2] = c2; cd[3] = c3; cd[4] = c4; cd[5] = c5;
    }
    red[tid] = p;                               // tid>=512 contribute 0
    __syncthreads();
    for (int st = 512; st > 0; st >>= 1) {
        if (tid < st) red[tid] = fmaxf(red[tid], red[tid + st]);
        __syncthreads();
    }
    if (tid == 0) g_maxp = red[0];
}

// ---------------- pairwise suppress bitmask (parallel) ----------------------
__global__ void k_pairs() {                     // grid 512, block 512
    int i = blockIdx.x, j = threadIdx.x;
    __shared__ float bi[6];
    if (j < 6) bi[j] = g_cand[i * 6 + j];
    __syncthreads();
    const float* bj = g_cand + j * 6;
    float x1i = bi[1] - bi[3] * 0.5f, y1i = bi[2] - bi[4] * 0.5f;
    float x2i = x1i + bi[3],          y2i = y1i + bi[4];
    float x1j = bj[1] - bj[3] * 0.5f, y1j = bj[2] - bj[4] * 0.5f;
    float x2j = x1j + bj[3],          y2j = y1j + bj[4];
    float iw = fmaxf(fminf(x2i, x2j) - fmaxf(x1i, x1j), 0.f);
    float ih = fmaxf(fminf(y2i, y2j) - fmaxf(y1i, y1j), 0.f);
    float inter = iw * ih;
    float ai = (x2i - x1i) * (y2i - y1i);
    float aj = (x2j - x1j) * (y2j - y1j);
    float iou = inter / (ai + aj - inter);
    bool sup = (bi[5] == bj[5]) || (iou >= 0.5f);
    unsigned m = __ballot_sync(0xffffffffu, sup);
    if ((j & 31) == 0) g_sup[i * 16 + (j >> 5)] = m;
}

// ---------------- serial NMS cascade + output --------------------------------
__global__ void k_nms(float* __restrict__ out, int out_size) {   // 1 block, 512
    __shared__ unsigned ssup[NK * 16];          // 32 KB
    __shared__ float    scand[NK * 6];          // 12 KB
    __shared__ unsigned salive[16];
    __shared__ unsigned skeep[16];
    int t = threadIdx.x;
    float maxp = g_maxp;
    float p = g_cand[t * 6];
    bool alive0 = (g_alive[t] != 0) && (p > 0.5f * maxp);
    unsigned ab = __ballot_sync(0xffffffffu, alive0);
    if ((t & 31) == 0) salive[t >> 5] = ab;
    for (int i = t; i < NK * 16; i += NK) ssup[i] = g_sup[i];
    for (int i = t; i < NK * 6;  i += NK) scand[i] = g_cand[i];
    __syncthreads();

    if (t < 32) {
        int l = t & 15;
        unsigned suppressed = ~salive[l];       // suppressed0 = !alive0
        unsigned keep = 0;
        for (int i = 0; i < NK; ++i) {
            int w = i >> 5, b = i & 31;
            unsigned sw  = __shfl_sync(0xffffffffu, suppressed, w);
            unsigned row = ssup[i * 16 + l];
            if (!((sw >> b) & 1u)) {            // active
                suppressed |= row;              // bits j<=i already consumed: harmless
                if (l == w) keep |= (1u << b);
            }
        }
        if (t < 16) skeep[l] = keep;
    }
    __syncthreads();

    bool kp = (skeep[t >> 5] >> (t & 31)) & 1u;
    float km = kp ? 1.f : 0.f;
    if (out_size >= NK * 6) {
#pragma unroll
        for (int c = 0; c < 6; ++c) out[t * 6 + c] = scand[t * 6 + c] * km;
    }
    if (out_size >= NK * 6 + NK) out[NK * 6 + t] = km;
    for (int i = NK * 7 + t; i < out_size; i += NK) out[i] = 0.f;  // safety fill
}

// ---------------- launch -----------------------------------------------------
extern "C" void kernel_launch(void* const* d_in, const int* in_sizes, int n_in,
                              void* d_out, int out_size) {
    const float* o13 = (const float*)d_in[0];
    const float* o26 = (const float*)d_in[1];
    const float* o52 = (const float*)d_in[2];
    const float* a13 = (const float*)d_in[3];
    const float* a26 = (const float*)d_in[4];
    const float* a52 = (const float*)d_in[5];
    const float* c1  = (const float*)d_in[6];
    const float* c2  = (const float*)d_in[7];
    float* out = (float*)d_out;

    const int N13 = 32 * 3 * 13 * 13;   // 16224
    const int N26 = 32 * 3 * 26 * 26;   // 64896
    const int N52 = 32 * 3 * 52 * 52;   // 259584

    k_init<<<16, 256>>>();
    k_decode<13><<<(N13 + 255) / 256, 256>>>(o13, a13, c1, c2, 0);
    k_decode<26><<<(N26 + 255) / 256, 256>>>(o26, a26, c1, c2, N13);
    k_decode<52><<<(N52 + 255) / 256, 256>>>(o52, a52, c1, c2, N13 + N26);
    k_select1<<<1, 1024>>>();
    k_hist2<<<(NT + 255) / 256, 256>>>();
    k_select2<<<1, 1024>>>();
    k_gather<<<(NT + 255) / 256, 256>>>();
    k_sort<<<1, 1024>>>();
    k_pairs<<<512, 512>>>();
    k_nms<<<1, 512>>>(out, out_size);
}

// round 2
// speedup vs baseline: 1.3272x; 1.3272x over previous
#include <cuda_runtime.h>
#include <cstdint>

typedef unsigned long long u64;
typedef unsigned u32;

#define NT    340704          // 32*3*(169+676+2704)
#define CAP   4096
#define NK    512
#define GRID  148
#define BLK   1024
#define NTH   (GRID*BLK)

#define G13 0
#define G26 16224
#define G52 81120

#define W52 64896             // 32*3*676  vec4 items for scale 52
#define W26 16224             // 32*3*169  vec4 items for scale 26
#define W13 16224             // scalar items for scale 13
#define WTOT (W52+W26+W13)    // 97344

// ---------------- scratch (static device globals: no allocation) ------------
__device__ u64   g_keys[NT];
__device__ float g_boxes[NT * 6];
__device__ u32   g_hist1[2048];
__device__ u32   g_hist2[2048];
__device__ u32   g_cnt;
__device__ int   g_b1, g_b2;
__device__ u32   g_cA1;
__device__ u64   g_gbuf[CAP];
__device__ float g_cand[NK * 6];
__device__ unsigned char g_alive[NK];
__device__ float g_maxp;
__device__ u32   g_sup[NK * 16];
__device__ u32   g_a0w[16];
__device__ u32   g_bar_arrive;
__device__ u32   g_bar_gen;

// order-preserving float -> uint mapping
__device__ __forceinline__ u32 fordf(float f) {
    u32 u = __float_as_uint(f);
    return (u & 0x80000000u) ? ~u : (u | 0x80000000u);
}

// software grid barrier: one block per SM guaranteed (GRID=148 <= SM count,
// launch_bounds(1024,1), 47KB static smem -> exactly 1 resident block/SM)
__device__ __forceinline__ void grid_barrier() {
    __syncthreads();
    __threadfence();
    if (threadIdx.x == 0) {
        volatile u32* vgen = &g_bar_gen;
        u32 gen = *vgen;
        __threadfence();                     // order gen read before arrive
        u32 a = atomicAdd(&g_bar_arrive, 1u);
        if (a == GRID - 1u) {
            g_bar_arrive = 0u;
            __threadfence();
            atomicAdd(&g_bar_gen, 1u);       // release
        } else {
            while (*vgen == gen) {}
        }
    }
    __threadfence();
    __syncthreads();
}

// ---------------- decode: 4 consecutive cells per thread (vec4) -------------
template <int S, int GOFF>
__device__ __forceinline__ void decode_v4(const float* __restrict__ out,
                                          const float* __restrict__ anc,
                                          float c1, float c2, int v, u32* shist) {
    const int SS = S * S, G4 = SS / 4;
    int plane = v / G4;
    int grp = v - plane * G4;
    int cell0 = grp * 4;
    int b = plane / 3, a = plane - 3 * b;
    const float* pc = out + ((size_t)b * 255 + (size_t)a * 85) * SS + cell0;
    float4 q0 = *(const float4*)pc;
    float4 q1 = *(const float4*)(pc + SS);
    float4 q2 = *(const float4*)(pc + 2 * SS);
    float4 q3 = *(const float4*)(pc + 3 * SS);
    float4 q4 = *(const float4*)(pc + 4 * SS);
    float m0 = -1e30f, m1 = -1e30f, m2 = -1e30f, m3 = -1e30f;
    float s0 = 0.f, s1 = 0.f, s2 = 0.f, s3 = 0.f;
    int i0 = 0, i1 = 0, i2 = 0, i3 = 0;
#pragma unroll 4
    for (int c = 0; c < 80; ++c) {
        float4 l = *(const float4*)(pc + (size_t)(5 + c) * SS);
        s0 += expf(l.x); if (l.x > m0) { m0 = l.x; i0 = c; }
        s1 += expf(l.y); if (l.y > m1) { m1 = l.y; i1 = c; }
        s2 += expf(l.z); if (l.z > m2) { m2 = l.z; i2 = c; }
        s3 += expf(l.w); if (l.w > m3) { m3 = l.w; i3 = c; }
    }
    const float sc = 416.f / (float)S;
    float an0 = anc[2 * a], an1 = anc[2 * a + 1];
    float o0a[4] = {q0.x, q0.y, q0.z, q0.w};
    float o1a[4] = {q1.x, q1.y, q1.z, q1.w};
    float o2a[4] = {q2.x, q2.y, q2.z, q2.w};
    float o3a[4] = {q3.x, q3.y, q3.z, q3.w};
    float o4a[4] = {q4.x, q4.y, q4.z, q4.w};
    float ma[4] = {m0, m1, m2, m3};
    float sa[4] = {s0, s1, s2, s3};
    int   ia[4] = {i0, i1, i2, i3};
#pragma unroll
    for (int k = 0; k < 4; ++k) {
        int cell = cell0 + k;
        int g = GOFF + (b * SS + cell) * 3 + a;
        float score = -1.f;
        if (o0a[k] > 0.f) {
            float obj = 1.f / (1.f + expf(-o0a[k]));
            float p = obj * expf(ma[k]) / sa[k];
            int y = cell / S, x = cell - y * S;
            float cx = ((float)x + o1a[k]) * sc / c1;
            float cy = ((float)y + o2a[k]) * sc / c2;
            float w  = expf(o3a[k]) * an0 / c1;
            float h  = expf(o4a[k]) * an1 / c2;
            float* bx = g_boxes + (size_t)g * 6;
            bx[0] = p; bx[1] = cx; bx[2] = cy; bx[3] = w; bx[4] = h; bx[5] = (float)ia[k];
            score = p;
        }
        u32 fs = fordf(score);
        g_keys[GOFF + plane * SS + cell] = ((u64)fs << 32) | (u32)(~(u32)g);
        atomicAdd(&shist[fs >> 21], 1u);
    }
}

__device__ __forceinline__ void decode_s13(const float* __restrict__ out,
                                           const float* __restrict__ anc,
                                           float c1, float c2, int v, u32* shist) {
    const int S = 13, SS = 169;
    int plane = v / SS;
    int cell = v - plane * SS;
    int b = plane / 3, a = plane - 3 * b;
    const float* pc = out + ((size_t)b * 255 + (size_t)a * 85) * SS + cell;
    float o0 = pc[0];
    int g = (b * SS + cell) * 3 + a;     // GOFF = 0
    float score = -1.f;
    if (o0 > 0.f) {
        float m = -1e30f, sum = 0.f; int am = 0;
#pragma unroll 4
        for (int c = 0; c < 80; ++c) {
            float l = pc[(size_t)(5 + c) * SS];
            sum += expf(l);
            if (l > m) { m = l; am = c; }
        }
        float obj = 1.f / (1.f + expf(-o0));
        float p = obj * expf(m) / sum;
        int y = cell / S, x = cell - y * S;
        const float sc = 416.f / 13.f;
        float cx = ((float)x + pc[SS]) * sc / c1;
        float cy = ((float)y + pc[2 * SS]) * sc / c2;
        float w  = expf(pc[3 * SS]) * anc[2 * a] / c1;
        float h  = expf(pc[4 * SS]) * anc[2 * a + 1] / c2;
        float* bx = g_boxes + (size_t)g * 6;
        bx[0] = p; bx[1] = cx; bx[2] = cy; bx[3] = w; bx[4] = h; bx[5] = (float)am;
        score = p;
    }
    u32 fs = fordf(score);
    g_keys[plane * SS + cell] = ((u64)fs << 32) | (u32)(~(u32)g);
    atomicAdd(&shist[fs >> 21], 1u);
}

// suffix-scan + threshold search over a 2048 histogram (single block)
__device__ __forceinline__ void suffix_select(u32* sa, u32* sb, const u32* ghist,
                                              u32 target, int* out_b, u32* out_above) {
    int tid = threadIdx.x;
    for (int i = tid; i < 2048; i += BLK) sa[i] = ghist[i];
    __syncthreads();
    u32 *src = sa, *dst = sb;
    for (int off = 1; off < 2048; off <<= 1) {
        for (int i = tid; i < 2048; i += BLK) {
            u32 v = src[i];
            if (i + off < 2048) v += src[i + off];
            dst[i] = v;
        }
        __syncthreads();
        u32* tmp = src; src = dst; dst = tmp;
    }
    for (int i = tid; i < 2048; i += BLK) {
        bool cross = (src[i] >= target) && (i == 2047 || src[i + 1] < target);
        if (cross) {
            *out_b = i;
            if (out_above) *out_above = (i == 2047) ? 0u : src[i + 1];
        }
    }
}

// ---------------- the megakernel ---------------------------------------------
__global__ void __launch_bounds__(BLK, 1) k_mega(
    const float* __restrict__ o13, const float* __restrict__ o26,
    const float* __restrict__ o52,
    const float* __restrict__ a13, const float* __restrict__ a26,
    const float* __restrict__ a52,
    const float* __restrict__ c1p, const float* __restrict__ c2p,
    float* __restrict__ out, int out_size)
{
    __shared__ __align__(16) unsigned char sm[47104];   // 46 KB union
    const int tid = threadIdx.x;
    const int gt = blockIdx.x * BLK + tid;

    // ===== P1a: zero global scratch + decode (shared hist) =====
    u32* shist = (u32*)sm;
    for (int i = tid; i < 2048; i += BLK) shist[i] = 0;
    if (gt < 2048) { g_hist1[gt] = 0; g_hist2[gt] = 0; }
    if (gt == NTH - 1) g_cnt = 0;
    __syncthreads();
    {
        float c1 = *c1p, c2 = *c2p;
        if (gt < W52)            decode_v4<52, G52>(o52, a52, c1, c2, gt, shist);
        else if (gt < W52 + W26) decode_v4<26, G26>(o26, a26, c1, c2, gt - W52, shist);
        else if (gt < WTOT)      decode_s13(o13, a13, c1, c2, gt - (W52 + W26), shist);
    }
    grid_barrier();                         // zeroing + decode done everywhere

    // ===== P1b: merge shared hist into global =====
    for (int i = tid; i < 2048; i += BLK) {
        u32 v = shist[i];
        if (v) atomicAdd(&g_hist1[i], v);
    }
    grid_barrier();

    // ===== P2: level-1 select (block 0) =====
    if (blockIdx.x == 0) {
        u32* sa = (u32*)sm; u32* sb = sa + 2048;
        suffix_select(sa, sb, g_hist1, (u32)NK, &g_b1, &g_cA1);
    }
    grid_barrier();

    // ===== P3: level-2 histogram =====
    {
        u32* sh2 = (u32*)sm;
        for (int i = tid; i < 2048; i += BLK) sh2[i] = 0;
        __syncthreads();
        int B1 = g_b1;
        for (int t = gt; t < NT; t += NTH) {
            u64 k = g_keys[t];
            if ((int)(u32)(k >> 53) == B1)
                atomicAdd(&sh2[(u32)(k >> 42) & 2047u], 1u);
        }
        __syncthreads();
        for (int i = tid; i < 2048; i += BLK) {
            u32 v = sh2[i];
            if (v) atomicAdd(&g_hist2[i], v);
        }
    }
    grid_barrier();

    // ===== P4: level-2 select (block 0) =====
    if (blockIdx.x == 0) {
        u32* sa = (u32*)sm; u32* sb = sa + 2048;
        u32 target = (u32)NK - g_cA1;       // >= 1
        suffix_select(sa, sb, g_hist2, target, &g_b2, 0);
    }
    grid_barrier();

    // ===== P5: gather candidates above (b1,b2) threshold =====
    {
        int B1 = g_b1, B2 = g_b2;
        for (int t = gt; t < NT; t += NTH) {
            u64 k = g_keys[t];
            int b1 = (int)(u32)(k >> 53);
            int b2 = (int)((u32)(k >> 42) & 2047u);
            if (b1 > B1 || (b1 == B1 && b2 >= B2)) {
                u32 pos = atomicAdd(&g_cnt, 1u);
                if (pos < (u32)CAP) g_gbuf[pos] = k;
            }
        }
    }
    grid_barrier();

    // ===== P6: exact top-512 by rank-select (block 0) =====
    if (blockIdx.x == 0) {
        u64* skeys = (u64*)sm;
        u32 cnt = g_cnt; if (cnt > (u32)CAP) cnt = CAP;
        for (u32 i = tid; i < cnt; i += BLK) skeys[i] = g_gbuf[i];
        for (int i = tid; i < NK * 6; i += BLK) g_cand[i] = 0.f;
        if (tid < NK) g_alive[tid] = 0;
        __syncthreads();
        for (u32 j = tid; j < cnt; j += BLK) {
            u64 kj = skeys[j];
            int r = 0; u32 i = 0;
            for (; i + 4 <= cnt; i += 4)
                r += (int)(skeys[i] > kj) + (int)(skeys[i+1] > kj)
                   + (int)(skeys[i+2] > kj) + (int)(skeys[i+3] > kj);
            for (; i < cnt; ++i) r += (int)(skeys[i] > kj);
            if (r < NK) {
                u32 fs = (u32)(kj >> 32);
                if (fs > 0x80000000u) {     // score > 0
                    u32 g = ~(u32)kj;
                    const float* bx = g_boxes + (size_t)g * 6;
                    float* cd = g_cand + r * 6;
                    cd[0] = bx[0]; cd[1] = bx[1]; cd[2] = bx[2];
                    cd[3] = bx[3]; cd[4] = bx[4]; cd[5] = bx[5];
                    g_alive[r] = 1;
                }
            }
        }
        __syncthreads();
        float p = 0.f;
        if (tid < NK && g_alive[tid]) p = g_cand[tid * 6];
        for (int o = 16; o > 0; o >>= 1) p = fmaxf(p, __shfl_xor_sync(0xffffffffu, p, o));
        __shared__ float sred[32];
        if ((tid & 31) == 0) sred[tid >> 5] = p;
        __syncthreads();
        if (tid < 32) {
            float v = sred[tid];
            for (int o = 16; o > 0; o >>= 1) v = fmaxf(v, __shfl_xor_sync(0xffffffffu, v, o));
            if (tid == 0) g_maxp = v;
        }
    }
    grid_barrier();

    // ===== P7: pairwise suppress bitmask (blocks 0..15) + alive0 (block 147) =====
    {
        int gw = blockIdx.x * (BLK / 32) + (tid >> 5);
        int lane = tid & 31;
        if (gw < NK) {
            int i = gw;
            float cx = g_cand[i*6+1], cy = g_cand[i*6+2];
            float w  = g_cand[i*6+3], h  = g_cand[i*6+4], cl = g_cand[i*6+5];
            float x1i = cx - w * 0.5f, y1i = cy - h * 0.5f;
            float x2i = x1i + w,       y2i = y1i + h;
            float ai = (x2i - x1i) * (y2i - y1i);
            for (int cw = 0; cw < 16; ++cw) {
                int j = (cw << 5) + lane;
                const float* bj = g_cand + j * 6;
                float wj = bj[3], hj = bj[4];
                float x1j = bj[1] - wj * 0.5f, y1j = bj[2] - hj * 0.5f;
                float x2j = x1j + wj,          y2j = y1j + hj;
                float iw = fmaxf(fminf(x2i, x2j) - fmaxf(x1i, x1j), 0.f);
                float ih = fmaxf(fminf(y2i, y2j) - fmaxf(y1i, y1j), 0.f);
                float inter = iw * ih;
                float aj = (x2j - x1j) * (y2j - y1j);
                float iou = inter / (ai + aj - inter);
                bool sup = (cl == bj[5]) || (iou >= 0.5f);
                u32 msk = __ballot_sync(0xffffffffu, sup);
                if (lane == 0) g_sup[i * 16 + cw] = msk;
            }
        }
        if (blockIdx.x == GRID - 1 && tid < NK) {
            float mp = g_maxp;
            bool a0 = (g_alive[tid] != 0) && (g_cand[tid * 6] > 0.5f * mp);
            u32 m = __ballot_sync(0xffffffffu, a0);
            if ((tid & 31) == 0) g_a0w[tid >> 5] = m;
        }
    }
    grid_barrier();

    // ===== P8: serial NMS cascade + output (block 0) =====
    if (blockIdx.x == 0) {
        u32* ssup = (u32*)sm;                       // 32 KB
        float* scand = (float*)(sm + 32768);        // 12 KB
        __shared__ u32 salive0[16];
        __shared__ u32 skeep[16];
        for (int i = tid; i < NK * 16; i += BLK) ssup[i] = g_sup[i];
        for (int i = tid; i < NK * 6;  i += BLK) scand[i] = g_cand[i];
        if (tid < 16) salive0[tid] = g_a0w[tid];
        __syncthreads();
        if (tid < 32) {
            int l = tid & 15;
            u32 sup = ~salive0[l];                  // suppressed0 = !alive0
            u32 keep = 0;
            for (int w = 0; w < 16; ++w) {
                u32 supw = __shfl_sync(0xffffffffu, sup, w);
#pragma unroll
                for (int b = 0; b < 32; ++b) {
                    int i = (w << 5) + b;
                    u32 rl = ssup[i * 16 + l];
                    u32 rw = __shfl_sync(0xffffffffu, rl, w);   // off the chain
                    if (!((supw >> b) & 1u)) {
                        sup  |= rl;
                        supw |= rw;
                        if (l == w) keep |= (1u << b);
                    }
                }
            }
            if (tid < 16) skeep[tid] = keep;
        }
        __syncthreads();
        if (tid < NK) {
            bool kp = (skeep[tid >> 5] >> (tid & 31)) & 1u;
            float km = kp ? 1.f : 0.f;
            if (out_size >= NK * 6) {
#pragma unroll
                for (int c = 0; c < 6; ++c) out[tid * 6 + c] = scand[tid * 6 + c] * km;
            }
            if (out_size >= NK * 7) out[NK * 6 + tid] = km;
        }
    }
    // tail fill (if the output buffer is larger than 512*7)
    for (int i = NK * 7 + gt; i < out_size; i += NTH) out[i] = 0.f;
}

// ---------------- launch: ONE kernel ------------------------------------------
extern "C" void kernel_launch(void* const* d_in, const int* in_sizes, int n_in,
                              void* d_out, int out_size) {
    k_mega<<<GRID, BLK>>>(
        (const float*)d_in[0], (const float*)d_in[1], (const float*)d_in[2],
        (const float*)d_in[3], (const float*)d_in[4], (const float*)d_in[5],
        (const float*)d_in[6], (const float*)d_in[7],
        (float*)d_out, out_size);
}

// round 4
// speedup vs baseline: 1.3605x; 1.0251x over previous
#include <cuda_runtime.h>
#include <cstdint>

typedef unsigned long long u64;
typedef unsigned u32;

#define N13   16224           // 32*3*169
#define N26   64896           // 32*3*676
#define N52   259584          // 32*3*2704
#define NT    340704
#define CAP   4096
#define NK    512
#define GRID  148
#define BLK   1024
#define NTH   (GRID*BLK)

// ---------------- scratch (static device globals: no allocation) ------------
__device__ u64   g_keys[NT];
__device__ float g_boxes[NT * 6];
__device__ u32   g_hist1[2048];
__device__ u32   g_hist2[2048];
__device__ u32   g_cnt;
__device__ u32   g_work;
__device__ u64   g_gbuf[CAP];
__device__ u32   g_bar_arrive;
__device__ u32   g_bar_gen;

__device__ __forceinline__ u32 fordf(float f) {
    u32 u = __float_as_uint(f);
    return (u & 0x80000000u) ? ~u : (u | 0x80000000u);
}

// grid barrier: exactly one block per SM (GRID=148, launch_bounds(1024,1))
__device__ __forceinline__ void grid_barrier() {
    __syncthreads();
    __threadfence();
    if (threadIdx.x == 0) {
        volatile u32* vgen = &g_bar_gen;
        u32 gen = *vgen;
        __threadfence();
        u32 a = atomicAdd(&g_bar_arrive, 1u);
        if (a == GRID - 1u) {
            g_bar_arrive = 0u;
            __threadfence();
            atomicAdd(&g_bar_gen, 1u);
        } else {
            while (*vgen == gen) {}
        }
    }
    __threadfence();
    __syncthreads();
}

// ---------------- scalar per-cell decode (templated on S) -------------------
template <int S>
__device__ __forceinline__ void decode_cell(u32 rel, u32 slot,
                                            const float* __restrict__ src,
                                            const float* __restrict__ anc,
                                            float c1, float c2, u32* shist) {
    const int SS = S * S;
    int plane = rel / SS;
    int cell  = rel - plane * SS;
    int b = plane / 3, a = plane - 3 * b;
    const float* pc = src + ((size_t)b * 255 + (size_t)a * 85) * SS + cell;
    float o0 = __ldcs(pc);
    u32 g = slot - rel + (u32)((b * SS + cell) * 3 + a);  // goff + ...
    float score = -1.f;
    // class loop: warp-uniform trip count; compute unconditionally
    float m = -1e30f, sum = 0.f; int am = 0;
    const float* cp = pc + (size_t)5 * SS;
#pragma unroll 8
    for (int c = 0; c < 80; ++c) {
        float l = __ldcs(cp);
        cp += SS;
        sum += expf(l);
        if (l > m) { m = l; am = c; }
    }
    if (o0 > 0.f) {
        float obj = 1.f / (1.f + expf(-o0));
        float p = obj * expf(m) / sum;
        int y = cell / S, x = cell - y * S;
        const float sc = 416.f / (float)S;
        float cx = ((float)x + __ldcs(pc + SS)) * sc / c1;
        float cy = ((float)y + __ldcs(pc + 2 * SS)) * sc / c2;
        float w  = expf(__ldcs(pc + 3 * SS)) * anc[2 * a] / c1;
        float h  = expf(__ldcs(pc + 4 * SS)) * anc[2 * a + 1] / c2;
        float* bx = g_boxes + (size_t)g * 6;
        bx[0] = p; bx[1] = cx; bx[2] = cy; bx[3] = w; bx[4] = h; bx[5] = (float)am;
        score = p;
    }
    u32 fs = fordf(score);
    g_keys[slot] = ((u64)fs << 32) | (u32)(~g);
    atomicAdd(&shist[fs >> 21], 1u);
}

// suffix scan of a 2048-bin histogram; find threshold bucket
__device__ __forceinline__ void suffix_select(u32* sa, u32* sb, const u32* ghist,
                                              u32 target, int* out_b, u32* out_above) {
    int tid = threadIdx.x;
    for (int i = tid; i < 2048; i += BLK) sa[i] = ghist[i];
    __syncthreads();
    u32 *src = sa, *dst = sb;
    for (int off = 1; off < 2048; off <<= 1) {
        for (int i = tid; i < 2048; i += BLK) {
            u32 v = src[i];
            if (i + off < 2048) v += src[i + off];
            dst[i] = v;
        }
        __syncthreads();
        u32* tmp = src; src = dst; dst = tmp;
    }
    for (int i = tid; i < 2048; i += BLK) {
        bool cross = (src[i] >= target) && (i == 2047 || src[i + 1] < target);
        if (cross) {
            *out_b = i;
            if (out_above) *out_above = (i == 2047) ? 0u : src[i + 1];
        }
    }
    __syncthreads();
}

// ---------------- megakernel --------------------------------------------------
__global__ void __launch_bounds__(BLK, 1) k_mega(
    const float* __restrict__ o13, const float* __restrict__ o26,
    const float* __restrict__ o52,
    const float* __restrict__ a13, const float* __restrict__ a26,
    const float* __restrict__ a52,
    const float* __restrict__ c1p, const float* __restrict__ c2p,
    float* __restrict__ out, int out_size)
{
    __shared__ __align__(16) unsigned char sm[47104];
    __shared__ int   s_b1, s_b2;
    __shared__ u32   s_cA1;
    __shared__ u32   s_cnt;
    __shared__ u32   s_a0w[16], s_keep[16];
    __shared__ int   s_aliveIdx[NK];
    __shared__ int   s_kOf[NK];
    __shared__ int   s_nA;
    __shared__ float s_red[32];
    __shared__ float s_maxp;

    const int tid = threadIdx.x;
    const int gt = blockIdx.x * BLK + tid;
    const int lane = tid & 31;

    // ===== P1: reset g_cnt (barrier-separated from all uses) + decode =====
    if (gt == NTH - 1) g_cnt = 0;
    {
        u32* shist = (u32*)sm;
        for (int i = tid; i < 2048; i += BLK) shist[i] = 0;
        __syncthreads();
        float c1 = *c1p, c2 = *c2p;
        for (;;) {
            u32 base = 0;
            if (lane == 0) base = atomicAdd(&g_work, 32u);
            base = __shfl_sync(0xffffffffu, base, 0);
            if (base >= (u32)NT) break;
            u32 u = base + (u32)lane;
            if (u < (u32)NT) {
                if (u < N13)             decode_cell<13>(u, u, o13, a13, c1, c2, shist);
                else if (u < N13 + N26)  decode_cell<26>(u - N13, u, o26, a26, c1, c2, shist);
                else                     decode_cell<52>(u - (N13 + N26), u, o52, a52, c1, c2, shist);
            }
        }
        __syncthreads();
        for (int i = tid; i < 2048; i += BLK) {
            u32 v = shist[i];
            if (v) atomicAdd(&g_hist1[i], v);
        }
    }
    grid_barrier();

    // ===== P2+P3: every block selects b1 (redundantly), then builds hist2 =====
    {
        u32* sa = (u32*)sm; u32* sb = sa + 2048;
        suffix_select(sa, sb, g_hist1, (u32)NK, &s_b1, &s_cA1);
        u32* sh2 = (u32*)sm;                        // reuse sa region (scan consumed)
        for (int i = tid; i < 2048; i += BLK) sh2[i] = 0;
        __syncthreads();
        int B1 = s_b1;
        for (int t = gt; t < NT; t += NTH) {
            u64 k = g_keys[t];
            if ((int)(u32)(k >> 53) == B1)
                atomicAdd(&sh2[(u32)(k >> 42) & 2047u], 1u);
        }
        __syncthreads();
        for (int i = tid; i < 2048; i += BLK) {
            u32 v = sh2[i];
            if (v) atomicAdd(&g_hist2[i], v);
        }
    }
    grid_barrier();

    // ===== P4+P5: every block selects b2, then gathers candidates =====
    {
        u32* sa = (u32*)sm; u32* sb = sa + 2048;
        suffix_select(sa, sb, g_hist2, (u32)NK - s_cA1, &s_b2, 0);
        int B1 = s_b1, B2 = s_b2;
        for (int t = gt; t < NT; t += NTH) {
            u64 k = g_keys[t];
            int b1 = (int)(u32)(k >> 53);
            int b2 = (int)((u32)(k >> 42) & 2047u);
            if (b1 > B1 || (b1 == B1 && b2 >= B2)) {
                u32 pos = atomicAdd(&g_cnt, 1u);
                if (pos < (u32)CAP) g_gbuf[pos] = k;
            }
        }
    }
    grid_barrier();   // last barrier

    // tail-fill of out beyond 512*7 (all blocks, disjoint from block-0 writes)
    for (int i = NK * 7 + gt; i < out_size; i += NTH) out[i] = 0.f;

    if (blockIdx.x == 1) {          // scratch reset for next graph replay
        for (int i = tid; i < 2048; i += BLK) { g_hist1[i] = 0; g_hist2[i] = 0; }
        if (tid == 0) g_work = 0;   // nothing reads these after the last barrier
    }
    if (blockIdx.x != 0) return;

    // =================== block 0: rank-select + NMS + output ===================
    u64*   skeys = (u64*)sm;                         // [0, 32768)
    float* scand = (float*)(sm + 32768);             // [32768, 45056)
    unsigned char* salive = (unsigned char*)(sm + 45056);   // 512 B

    if (tid == 0) { s_cnt = g_cnt; s_nA = 0; }       // single reader; no reset here
    __syncthreads();
    u32 cnt = s_cnt; if (cnt > (u32)CAP) cnt = CAP;
    for (u32 i = tid; i < cnt; i += BLK) skeys[i] = g_gbuf[i];
    for (int i = tid; i < NK * 6; i += BLK) scand[i] = 0.f;
    if (tid < NK) salive[tid] = 0;
    __syncthreads();

    // exact ranks (keys unique), fill candidate table
    for (u32 j = tid; j < cnt; j += BLK) {
        u64 kj = skeys[j];
        int r = 0; u32 i = 0;
        for (; i + 4 <= cnt; i += 4)
            r += (int)(skeys[i] > kj) + (int)(skeys[i+1] > kj)
               + (int)(skeys[i+2] > kj) + (int)(skeys[i+3] > kj);
        for (; i < cnt; ++i) r += (int)(skeys[i] > kj);
        if (r < NK && (u32)(kj >> 32) > 0x80000000u) {   // score > 0
            u32 g = ~(u32)kj;
            const float* bx = g_boxes + (size_t)g * 6;
            float* cd = scand + r * 6;
            cd[0] = bx[0]; cd[1] = bx[1]; cd[2] = bx[2];
            cd[3] = bx[3]; cd[4] = bx[4]; cd[5] = bx[5];
            salive[r] = 1;
        }
    }
    __syncthreads();

    // maxp over alive candidates
    {
        float p = 0.f;
        if (tid < NK && salive[tid]) p = scand[tid * 6];
        for (int o = 16; o > 0; o >>= 1) p = fmaxf(p, __shfl_xor_sync(0xffffffffu, p, o));
        if (lane == 0) s_red[tid >> 5] = p;
        __syncthreads();
        if (tid < 32) {
            float v = s_red[tid];
            for (int o = 16; o > 0; o >>= 1) v = fmaxf(v, __shfl_xor_sync(0xffffffffu, v, o));
            if (tid == 0) s_maxp = v;
        }
        __syncthreads();
    }

    // alive0 mask + compaction of alive rows
    if (tid < NK) {
        bool a0 = salive[tid] && (scand[tid * 6] > 0.5f * s_maxp);
        u32 m = __ballot_sync(0xffffffffu, a0);
        if (lane == 0) s_a0w[tid >> 5] = m;
        if (a0) {
            int k = atomicAdd(&s_nA, 1);
            s_aliveIdx[k] = tid;
            s_kOf[tid] = k;
        }
    }
    __syncthreads();

    // IoU suppress rows ONLY for alive0 candidates (reuse skeys region)
    u32* ssup = (u32*)sm;                     // nA*16 u32 <= 32 KB
    {
        int nA = s_nA;
        int w = tid >> 5;
        for (int k = w; k < nA; k += 32) {
            int i = s_aliveIdx[k];
            float cxi = scand[i*6+1], cyi = scand[i*6+2];
            float wi  = scand[i*6+3], hi  = scand[i*6+4], cli = scand[i*6+5];
            float x1i = cxi - wi * 0.5f, y1i = cyi - hi * 0.5f;
            float x2i = x1i + wi,        y2i = y1i + hi;
            float ai = (x2i - x1i) * (y2i - y1i);
            for (int cw = 0; cw < 16; ++cw) {
                int j = (cw << 5) + lane;
                const float* bj = scand + j * 6;
                float wj = bj[3], hj = bj[4];
                float x1j = bj[1] - wj * 0.5f, y1j = bj[2] - hj * 0.5f;
                float x2j = x1j + wj,          y2j = y1j + hj;
                float iw = fmaxf(fminf(x2i, x2j) - fmaxf(x1i, x1j), 0.f);
                float ih = fmaxf(fminf(y2i, y2j) - fmaxf(y1i, y1j), 0.f);
                float inter = iw * ih;
                float aj = (x2j - x1j) * (y2j - y1j);
                float iou = inter / (ai + aj - inter);
                bool sup = (cli == bj[5]) || (iou >= 0.5f);
                u32 msk = __ballot_sync(0xffffffffu, sup);
                if (lane == 0) ssup[k * 16 + cw] = msk;
            }
        }
    }
    __syncthreads();

    // serial cascade with ffs-skip (single thread; work ~ #keeps)
    if (tid == 0) {
        u32 sup[16], keep[16];
#pragma unroll
        for (int x = 0; x < 16; ++x) { sup[x] = ~s_a0w[x]; keep[x] = 0u; }
        for (int w = 0; w < 16; ++w) {
            u32 avail = ~sup[w];
            while (avail) {
                int b = __ffs(avail) - 1;
                int i = (w << 5) + b;
                keep[w] |= (1u << b);
                int k = s_kOf[i];
#pragma unroll
                for (int x = 0; x < 16; ++x) sup[x] |= ssup[k * 16 + x];
                u32 hi = (b == 31) ? 0u : (0xffffffffu << (b + 1));
                avail = ~sup[w] & hi;
            }
        }
#pragma unroll
        for (int x = 0; x < 16; ++x) s_keep[x] = keep[x];
    }
    __syncthreads();

    // output
    if (tid < NK) {
        bool kp = (s_keep[tid >> 5] >> (tid & 31)) & 1u;
        float km = kp ? 1.f : 0.f;
        if (out_size >= NK * 6) {
#pragma unroll
            for (int c = 0; c < 6; ++c) out[tid * 6 + c] = scand[tid * 6 + c] * km;
        }
        if (out_size >= NK * 7) out[NK * 6 + tid] = km;
    }
}

// ---------------- launch: ONE kernel ------------------------------------------
extern "C" void kernel_launch(void* const* d_in, const int* in_sizes, int n_in,
                              void* d_out, int out_size) {
    k_mega<<<GRID, BLK>>>(
        (const float*)d_in[0], (const float*)d_in[1], (const float*)d_in[2],
        (const float*)d_in[3], (const float*)d_in[4], (const float*)d_in[5],
        (const float*)d_in[6], (const float*)d_in[7],
        (float*)d_out, out_size);
}